// round 1
// baseline (speedup 1.0000x reference)
#include <cuda_runtime.h>
#include <cstdint>

// FISTA denoiser: min ||y-x||^2 + LAM*||diff(x,2)||^2 s.t. 0<=x<=y, per row of 512.
// One warp per row, 16 elements per lane in registers, 2-element halo via shfl.
// Both passes fused (pass2 re-solves same rows with y = pass1 output).

#define LAM   10.0f
#define NIT   100
#define ROWN  512
#define EPL   16          // elements per lane

// step = 1 / (2*(1+16*LAM)); A = 2*step; B = 2*LAM*step
__device__ __forceinline__ float stepA() { return 1.0f / (1.0f + 16.0f * LAM); }          // 1/161
__device__ __forceinline__ float stepB() { return LAM / (1.0f + 16.0f * LAM); }           // 10/161

__device__ __forceinline__ void solve_row(const float* __restrict__ y,
                                          float* __restrict__ x,
                                          int lane)
{
    const float A = stepA();
    const float B = stepB();
    const unsigned FULL = 0xffffffffu;

    float z[EPL];
    #pragma unroll
    for (int i = 0; i < EPL; i++) {
        // proj(y) onto [0,y] == y for all y (clip = min(max(v,0),y))
        float v = fminf(fmaxf(y[i], 0.0f), y[i]);
        x[i] = v;
        z[i] = v;
    }

    float t = 1.0f;

    for (int it = 0; it < NIT; ++it) {
        // halo exchange: z[-2], z[-1] from lane-1; z[16], z[17] from lane+1
        float zl0 = __shfl_up_sync  (FULL, z[EPL - 2], 1);
        float zl1 = __shfl_up_sync  (FULL, z[EPL - 1], 1);
        float zr0 = __shfl_down_sync(FULL, z[0], 1);
        float zr1 = __shfl_down_sync(FULL, z[1], 1);

        // extended z: ze[k] = z_global[16*lane - 2 + k], k = 0..19
        float ze[EPL + 4];
        ze[0] = zl0; ze[1] = zl1;
        #pragma unroll
        for (int i = 0; i < EPL; i++) ze[2 + i] = z[i];
        ze[EPL + 2] = zr0; ze[EPL + 3] = zr1;

        // d[k] = z[j] - 2 z[j+1] + z[j+2], j = 16*lane - 2 + k ; valid iff 0 <= j <= 509
        float d[EPL + 2];
        #pragma unroll
        for (int k = 0; k < EPL + 2; k++)
            d[k] = fmaf(-2.0f, ze[k + 1], ze[k]) + ze[k + 2];

        // boundary masking: only lane 0 (j<0) and lane 31 (j>509) have invalid entries
        if (lane == 0)  { d[0] = 0.0f; d[1] = 0.0f; }
        if (lane == 31) { d[EPL] = 0.0f; d[EPL + 1] = 0.0f; }

        // FISTA momentum coefficients (scalar, identical across lanes)
        float tn = 0.5f * (1.0f + sqrtf(fmaf(4.0f * t, t, 1.0f)));
        float m  = (t - 1.0f) / tn;
        t = tn;

        #pragma unroll
        for (int i = 0; i < EPL; i++) {
            // DtD[i] = d[i] - 2 d[i+1] + d[i+2]   (local index shift of +2)
            float dtd = fmaf(-2.0f, d[i + 1], d[i]) + d[i + 2];
            // v = z - A*(z-y) - B*dtd  ==  z - step*(2(z-y) + 2*LAM*DtD(z))
            float v  = fmaf(-A, z[i] - y[i], z[i]);
            v        = fmaf(-B, dtd, v);
            float xn = fminf(fmaxf(v, 0.0f), y[i]);   // proj onto [0, y]
            float zn = fmaf(m, xn - x[i], xn);
            x[i] = xn;
            z[i] = zn;
        }
    }
}

__global__ void __launch_bounds__(256, 2)
fista_denoise_kernel(const float* __restrict__ in, float* __restrict__ out, int nrows)
{
    const int gwarp = (int)((blockIdx.x * (unsigned)blockDim.x + threadIdx.x) >> 5);
    const int lane  = threadIdx.x & 31;
    if (gwarp >= nrows) return;   // whole warp exits together (no shfl divergence)

    const float* rp = in  + (size_t)gwarp * ROWN + lane * EPL;
    float*       wp = out + (size_t)gwarp * ROWN + lane * EPL;

    float y[EPL];
    #pragma unroll
    for (int v = 0; v < EPL / 4; v++) {
        float4 q = reinterpret_cast<const float4*>(rp)[v];
        y[4 * v + 0] = q.x; y[4 * v + 1] = q.y;
        y[4 * v + 2] = q.z; y[4 * v + 3] = q.w;
    }

    float x[EPL];
    solve_row(y, x, lane);          // pass 1: y = input
    #pragma unroll
    for (int i = 0; i < EPL; i++) y[i] = x[i];
    solve_row(y, x, lane);          // pass 2: y = pass-1 output (same rows)

    #pragma unroll
    for (int v = 0; v < EPL / 4; v++) {
        float4 q;
        q.x = x[4 * v + 0]; q.y = x[4 * v + 1];
        q.z = x[4 * v + 2]; q.w = x[4 * v + 3];
        reinterpret_cast<float4*>(wp)[v] = q;
    }
}

extern "C" void kernel_launch(void* const* d_in, const int* in_sizes, int n_in,
                              void* d_out, int out_size)
{
    const float* in = (const float*)d_in[0];
    float* out = (float*)d_out;
    const int nelem = in_sizes[0];          // 32*512*512
    const int nrows = nelem / ROWN;         // 16384
    const int warps_per_block = 256 / 32;   // 8
    const int nblocks = (nrows + warps_per_block - 1) / warps_per_block;
    fista_denoise_kernel<<<nblocks, 256>>>(in, out, nrows);
}

// round 2
// speedup vs baseline: 1.2725x; 1.2725x over previous
#include <cuda_runtime.h>
#include <cstdint>

// FISTA denoiser, packed f32x2 version.
// Layout: one warp = TWO rows (2w, 2w+1). Each 64-bit register packs
// (row0[i], row1[i]) so every stencil / FMA / momentum op is a single
// packed f32x2 instruction with no cross-half shifts.
// 16 element-indices per lane, halo via 64-bit shuffles.

#define LAM   10.0f
#define NIT   100
#define ROWN  512
#define EPL   16

typedef unsigned long long u64;

__device__ __forceinline__ u64 pk(float lo, float hi) {
    u64 r; asm("mov.b64 %0, {%1,%2};" : "=l"(r) : "f"(lo), "f"(hi)); return r;
}
__device__ __forceinline__ void upk(u64 v, float& lo, float& hi) {
    asm("mov.b64 {%0,%1}, %2;" : "=f"(lo), "=f"(hi) : "l"(v));
}
__device__ __forceinline__ u64 fma2(u64 a, u64 b, u64 c) {
    u64 d; asm("fma.rn.f32x2 %0, %1, %2, %3;" : "=l"(d) : "l"(a), "l"(b), "l"(c)); return d;
}
__device__ __forceinline__ u64 add2(u64 a, u64 b) {
    u64 d; asm("add.rn.f32x2 %0, %1, %2;" : "=l"(d) : "l"(a), "l"(b)); return d;
}
__device__ __forceinline__ u64 mul2(u64 a, u64 b) {
    u64 d; asm("mul.rn.f32x2 %0, %1, %2;" : "=l"(d) : "l"(a), "l"(b)); return d;
}
__device__ __forceinline__ u64 bc(float f) { return pk(f, f); }

// A = 1/(1+16*LAM), B = LAM/(1+16*LAM)  (= 2*step and 2*LAM*step)
__device__ __forceinline__ float cA() { return 1.0f / (1.0f + 16.0f * LAM); }
__device__ __forceinline__ float cB() { return LAM  / (1.0f + 16.0f * LAM); }

// One FISTA solve on the packed pair-of-rows held in y/x/z (all packed).
__device__ __forceinline__ void solve2(const u64* __restrict__ y,
                                       u64* __restrict__ x,
                                       int lane)
{
    const unsigned FULL = 0xffffffffu;
    const u64 CM2  = bc(-2.0f);           // stencil coefficient
    const u64 C1MA = bc(1.0f - cA());     // (1-A)
    const u64 CA   = bc(cA());            // A
    const u64 CNB  = bc(-cB());           // -B

    u64 z[EPL];
    #pragma unroll
    for (int i = 0; i < EPL; i++) { x[i] = y[i]; z[i] = y[i]; }  // proj(y)=y on [0,y]

    float t = 1.0f;

    for (int it = 0; it < NIT; ++it) {
        // 64-bit halo shuffles: z[-2],z[-1] from lane-1 ; z[16],z[17] from lane+1
        u64 zm2 = __shfl_up_sync  (FULL, z[EPL - 2], 1);
        u64 zm1 = __shfl_up_sync  (FULL, z[EPL - 1], 1);
        u64 zp0 = __shfl_down_sync(FULL, z[0], 1);
        u64 zp1 = __shfl_down_sync(FULL, z[1], 1);

        // ze[k] = z_global[16*lane - 2 + k], k = 0..19  (packed over both rows)
        u64 ze[EPL + 4];
        ze[0] = zm2; ze[1] = zm1;
        #pragma unroll
        for (int i = 0; i < EPL; i++) ze[2 + i] = z[i];
        ze[EPL + 2] = zp0; ze[EPL + 3] = zp1;

        // d[k] = ze[k] - 2 ze[k+1] + ze[k+2] ; global j = 16*lane - 2 + k,
        // valid iff 0 <= j <= 509  -> mask lane 0 (k=0,1) and lane 31 (k=16,17)
        u64 d[EPL + 2];
        #pragma unroll
        for (int k = 0; k < EPL + 2; k++)
            d[k] = add2(fma2(CM2, ze[k + 1], ze[k]), ze[k + 2]);
        if (lane == 0)  { d[0] = 0ull; d[1] = 0ull; }
        if (lane == 31) { d[EPL] = 0ull; d[EPL + 1] = 0ull; }

        // FISTA momentum scalars (identical across lanes)
        float tn = 0.5f * (1.0f + sqrtf(fmaf(4.0f * t, t, 1.0f)));
        float m  = (t - 1.0f) / tn;
        t = tn;
        const u64 M1P = bc(1.0f + m);
        const u64 MN  = bc(-m);

        #pragma unroll
        for (int i = 0; i < EPL; i++) {
            // DtD = d[i] - 2 d[i+1] + d[i+2]
            u64 dtd = add2(fma2(CM2, d[i + 1], d[i]), d[i + 2]);
            // v = (1-A) z + A y - B dtd   ==  z - step*(2(z-y) + 2*LAM*DtD(z))
            u64 v = fma2(C1MA, z[i], fma2(CA, y[i], mul2(CNB, dtd)));
            // clamp onto [0, y] — scalar FMNMX on the alu pipe (unpack is free)
            float vl, vh, yl, yh;
            upk(v, vl, vh);
            upk(y[i], yl, yh);
            float xl = fminf(fmaxf(vl, 0.0f), yl);
            float xh = fminf(fmaxf(vh, 0.0f), yh);
            u64 xn = pk(xl, xh);
            // z_new = (1+m) x_new - m x_old
            u64 zn = fma2(M1P, xn, mul2(MN, x[i]));
            x[i] = xn;
            z[i] = zn;
        }
    }
}

__global__ void __launch_bounds__(128)
fista_denoise2_kernel(const float* __restrict__ in, float* __restrict__ out, int npairs)
{
    const int gwarp = (int)((blockIdx.x * (unsigned)blockDim.x + threadIdx.x) >> 5);
    const int lane  = threadIdx.x & 31;
    if (gwarp >= npairs) return;   // whole warp exits together

    const float* r0 = in + (size_t)(2 * gwarp) * ROWN + lane * EPL;
    const float* r1 = r0 + ROWN;

    u64 y[EPL];
    #pragma unroll
    for (int v = 0; v < EPL / 4; v++) {
        float4 a = reinterpret_cast<const float4*>(r0)[v];
        float4 b = reinterpret_cast<const float4*>(r1)[v];
        y[4 * v + 0] = pk(a.x, b.x);
        y[4 * v + 1] = pk(a.y, b.y);
        y[4 * v + 2] = pk(a.z, b.z);
        y[4 * v + 3] = pk(a.w, b.w);
    }

    u64 x[EPL];
    solve2(y, x, lane);                       // pass 1: y = input
    #pragma unroll
    for (int i = 0; i < EPL; i++) y[i] = x[i];
    solve2(y, x, lane);                       // pass 2: y = pass-1 output

    float* w0 = out + (size_t)(2 * gwarp) * ROWN + lane * EPL;
    float* w1 = w0 + ROWN;
    #pragma unroll
    for (int v = 0; v < EPL / 4; v++) {
        float4 a, b;
        upk(x[4 * v + 0], a.x, b.x);
        upk(x[4 * v + 1], a.y, b.y);
        upk(x[4 * v + 2], a.z, b.z);
        upk(x[4 * v + 3], a.w, b.w);
        reinterpret_cast<float4*>(w0)[v] = a;
        reinterpret_cast<float4*>(w1)[v] = b;
    }
}

extern "C" void kernel_launch(void* const* d_in, const int* in_sizes, int n_in,
                              void* d_out, int out_size)
{
    const float* in = (const float*)d_in[0];
    float* out = (float*)d_out;
    const int nelem  = in_sizes[0];           // 32*512*512
    const int nrows  = nelem / ROWN;          // 16384
    const int npairs = nrows / 2;             // 8192 warps
    const int warps_per_block = 128 / 32;     // 4
    const int nblocks = (npairs + warps_per_block - 1) / warps_per_block;
    fista_denoise2_kernel<<<nblocks, 128>>>(in, out, npairs);
}

// round 3
// speedup vs baseline: 1.4968x; 1.1763x over previous
#include <cuda_runtime.h>
#include <cstdint>

// FISTA denoiser, packed f32x2, fused 5-point stencil + constexpr momentum table.
// One warp = two rows; each u64 register packs (row0[i], row1[i]).

#define LAM   10.0f
#define NIT   100
#define ROWN  512
#define EPL   16

typedef unsigned long long u64;

__device__ __forceinline__ u64 pk(float lo, float hi) {
    u64 r; asm("mov.b64 %0, {%1,%2};" : "=l"(r) : "f"(lo), "f"(hi)); return r;
}
__device__ __forceinline__ void upk(u64 v, float& lo, float& hi) {
    asm("mov.b64 {%0,%1}, %2;" : "=f"(lo), "=f"(hi) : "l"(v));
}
__device__ __forceinline__ u64 fma2(u64 a, u64 b, u64 c) {
    u64 d; asm("fma.rn.f32x2 %0, %1, %2, %3;" : "=l"(d) : "l"(a), "l"(b), "l"(c)); return d;
}
__device__ __forceinline__ u64 add2(u64 a, u64 b) {
    u64 d; asm("add.rn.f32x2 %0, %1, %2;" : "=l"(d) : "l"(a), "l"(b)); return d;
}
__device__ __forceinline__ u64 mul2(u64 a, u64 b) {
    u64 d; asm("mul.rn.f32x2 %0, %1, %2;" : "=l"(d) : "l"(a), "l"(b)); return d;
}
__device__ __forceinline__ u64 bc(float f) { return pk(f, f); }

// A = 1/(1+16*LAM) = 2*step ; B = LAM/(1+16*LAM) = 2*LAM*step
#define C_A (1.0f / (1.0f + 16.0f * LAM))
#define C_B (LAM  / (1.0f + 16.0f * LAM))

// ---- compile-time FISTA momentum table: m1p = 1+m, mn = -m per iteration ----
struct MTab { float m1p[NIT]; float mn[NIT]; };
constexpr MTab make_mtab() {
    MTab t{};
    double tt = 1.0;
    for (int i = 0; i < NIT; i++) {
        double s = 1.0 + 4.0 * tt * tt;
        double r = s;                         // Newton sqrt
        for (int k = 0; k < 64; k++) r = 0.5 * (r + s / r);
        double tn = 0.5 * (1.0 + r);
        double m  = (tt - 1.0) / tn;
        t.m1p[i] = (float)(1.0 + m);
        t.mn[i]  = (float)(-m);
        tt = tn;
    }
    return t;
}
__constant__ MTab c_mtab = make_mtab();

// One FISTA solve on the packed pair-of-rows. y: data (packed), x: output (packed).
__device__ __forceinline__ void solve2(const u64* __restrict__ y,
                                       u64* __restrict__ x,
                                       int lane)
{
    const unsigned FULL = 0xffffffffu;
    const u64 C0 = bc(1.0f - C_A - 6.0f * C_B);   // center tap
    const u64 C1 = bc(4.0f * C_B);                // +/-1 taps
    const u64 C2 = bc(-C_B);                      // +/-2 taps
    const u64 B5 = bc(5.0f * C_B);
    const u64 BN2 = bc(-2.0f * C_B);
    const u64 B1 = bc(C_B);

    // hoist A*y out of the iteration loop
    u64 ay[EPL];
    const u64 CA = bc(C_A);
    #pragma unroll
    for (int i = 0; i < EPL; i++) ay[i] = mul2(CA, y[i]);

    u64 z[EPL];
    #pragma unroll
    for (int i = 0; i < EPL; i++) { x[i] = y[i]; z[i] = y[i]; }  // proj(y)=y on [0,y]

    const bool l0 = (lane == 0), l31 = (lane == 31);

    for (int it = 0; it < NIT; ++it) {
        // 64-bit halo shuffles; zero-pad outside [0, 511]
        u64 zm2 = __shfl_up_sync  (FULL, z[EPL - 2], 1);
        u64 zm1 = __shfl_up_sync  (FULL, z[EPL - 1], 1);
        u64 zp0 = __shfl_down_sync(FULL, z[0], 1);
        u64 zp1 = __shfl_down_sync(FULL, z[1], 1);
        if (l0)  { zm2 = 0ull; zm1 = 0ull; }
        if (l31) { zp0 = 0ull; zp1 = 0ull; }

        // ze[k] = z_global[16*lane - 2 + k], k = 0..19
        u64 ze[EPL + 4];
        ze[0] = zm2; ze[1] = zm1;
        #pragma unroll
        for (int i = 0; i < EPL; i++) ze[2 + i] = z[i];
        ze[EPL + 2] = zp0; ze[EPL + 3] = zp1;

        // momentum coefficients from constant table (uniform)
        const u64 M1P = bc(c_mtab.m1p[it]);
        const u64 MN  = bc(c_mtab.mn[it]);

        u64 v[EPL];
        #pragma unroll
        for (int i = 0; i < EPL; i++) {
            // v = c0*z + c1*(z[-1]+z[+1]) + c2*(z[-2]+z[+2]) + A*y  (zero-padded 5-point)
            u64 s1 = add2(ze[i + 1], ze[i + 3]);
            u64 s2 = add2(ze[i],     ze[i + 4]);
            u64 t0 = fma2(C0, ze[i + 2], ay[i]);
            t0 = fma2(C1, s1, t0);
            v[i] = fma2(C2, s2, t0);
        }

        // exact boundary corrections (true D^T D differs from zero-padded 5-point
        // at global i = 0, 1, 510, 511):
        //   v0   += 5B z0 - 2B z1 ;  v1   += -2B z0 + B z1
        //   v510 += -2B z511 + B z510 ;  v511 += 5B z511 - 2B z510
        if (l0) {
            v[0] = fma2(B5,  z[0], v[0]);
            v[0] = fma2(BN2, z[1], v[0]);
            v[1] = fma2(BN2, z[0], v[1]);
            v[1] = fma2(B1,  z[1], v[1]);
        }
        if (l31) {
            v[EPL - 2] = fma2(BN2, z[EPL - 1], v[EPL - 2]);
            v[EPL - 2] = fma2(B1,  z[EPL - 2], v[EPL - 2]);
            v[EPL - 1] = fma2(B5,  z[EPL - 1], v[EPL - 1]);
            v[EPL - 1] = fma2(BN2, z[EPL - 2], v[EPL - 1]);
        }

        #pragma unroll
        for (int i = 0; i < EPL; i++) {
            // clamp onto [0, y] — scalar FMNMX on alu pipe (unpack is free)
            float vl, vh, yl, yh;
            upk(v[i], vl, vh);
            upk(y[i], yl, yh);
            float xl = fminf(fmaxf(vl, 0.0f), yl);
            float xh = fminf(fmaxf(vh, 0.0f), yh);
            u64 xn = pk(xl, xh);
            // z_new = (1+m) x_new - m x_old
            u64 zn = fma2(M1P, xn, mul2(MN, x[i]));
            x[i] = xn;
            z[i] = zn;
        }
    }
}

__global__ void __launch_bounds__(128, 3)
fista_denoise3_kernel(const float* __restrict__ in, float* __restrict__ out, int npairs)
{
    const int gwarp = (int)((blockIdx.x * (unsigned)blockDim.x + threadIdx.x) >> 5);
    const int lane  = threadIdx.x & 31;
    if (gwarp >= npairs) return;   // whole warp exits together

    const float* r0 = in + (size_t)(2 * gwarp) * ROWN + lane * EPL;
    const float* r1 = r0 + ROWN;

    u64 y[EPL];
    #pragma unroll
    for (int v = 0; v < EPL / 4; v++) {
        float4 a = reinterpret_cast<const float4*>(r0)[v];
        float4 b = reinterpret_cast<const float4*>(r1)[v];
        y[4 * v + 0] = pk(a.x, b.x);
        y[4 * v + 1] = pk(a.y, b.y);
        y[4 * v + 2] = pk(a.z, b.z);
        y[4 * v + 3] = pk(a.w, b.w);
    }

    u64 x[EPL];
    solve2(y, x, lane);                       // pass 1: y = input
    #pragma unroll
    for (int i = 0; i < EPL; i++) y[i] = x[i];
    solve2(y, x, lane);                       // pass 2: y = pass-1 output

    float* w0 = out + (size_t)(2 * gwarp) * ROWN + lane * EPL;
    float* w1 = w0 + ROWN;
    #pragma unroll
    for (int v = 0; v < EPL / 4; v++) {
        float4 a, b;
        upk(x[4 * v + 0], a.x, b.x);
        upk(x[4 * v + 1], a.y, b.y);
        upk(x[4 * v + 2], a.z, b.z);
        upk(x[4 * v + 3], a.w, b.w);
        reinterpret_cast<float4*>(w0)[v] = a;
        reinterpret_cast<float4*>(w1)[v] = b;
    }
}

extern "C" void kernel_launch(void* const* d_in, const int* in_sizes, int n_in,
                              void* d_out, int out_size)
{
    const float* in = (const float*)d_in[0];
    float* out = (float*)d_out;
    const int nelem  = in_sizes[0];           // 32*512*512
    const int nrows  = nelem / ROWN;          // 16384
    const int npairs = nrows / 2;             // 8192 warps
    const int warps_per_block = 128 / 32;     // 4
    const int nblocks = (npairs + warps_per_block - 1) / warps_per_block;
    fista_denoise3_kernel<<<nblocks, 128>>>(in, out, npairs);
}

// round 4
// speedup vs baseline: 1.5017x; 1.0033x over previous
#include <cuda_runtime.h>
#include <cstdint>

// FISTA denoiser, packed f32x2, fused 5-point stencil, occupancy-4 build.
// One warp = two rows; each u64 register packs (row0[i], row1[i]).

#define LAM   10.0f
#define NIT   100
#define ROWN  512
#define EPL   16

typedef unsigned long long u64;

__device__ __forceinline__ u64 pk(float lo, float hi) {
    u64 r; asm("mov.b64 %0, {%1,%2};" : "=l"(r) : "f"(lo), "f"(hi)); return r;
}
__device__ __forceinline__ void upk(u64 v, float& lo, float& hi) {
    asm("mov.b64 {%0,%1}, %2;" : "=f"(lo), "=f"(hi) : "l"(v));
}
__device__ __forceinline__ u64 fma2(u64 a, u64 b, u64 c) {
    u64 d; asm("fma.rn.f32x2 %0, %1, %2, %3;" : "=l"(d) : "l"(a), "l"(b), "l"(c)); return d;
}
__device__ __forceinline__ u64 add2(u64 a, u64 b) {
    u64 d; asm("add.rn.f32x2 %0, %1, %2;" : "=l"(d) : "l"(a), "l"(b)); return d;
}
__device__ __forceinline__ u64 mul2(u64 a, u64 b) {
    u64 d; asm("mul.rn.f32x2 %0, %1, %2;" : "=l"(d) : "l"(a), "l"(b)); return d;
}
__device__ __forceinline__ u64 bc(float f) { return pk(f, f); }

// A = 1/(1+16*LAM) = 2*step ; B = LAM/(1+16*LAM) = 2*LAM*step
#define C_A (1.0f / (1.0f + 16.0f * LAM))
#define C_B (LAM  / (1.0f + 16.0f * LAM))

// ---- compile-time FISTA momentum table, pre-broadcast as u64 f32x2 pairs ----
constexpr u64 bcast_bits(float f) {
    unsigned b = __builtin_bit_cast(unsigned, f);
    return ((u64)b << 32) | (u64)b;
}
struct MTab { u64 m1p[NIT]; u64 mn[NIT]; };
constexpr MTab make_mtab() {
    MTab t{};
    double tt = 1.0;
    for (int i = 0; i < NIT; i++) {
        double s = 1.0 + 4.0 * tt * tt;
        double r = s;                         // Newton sqrt
        for (int k = 0; k < 64; k++) r = 0.5 * (r + s / r);
        double tn = 0.5 * (1.0 + r);
        double m  = (tt - 1.0) / tn;
        t.m1p[i] = bcast_bits((float)(1.0 + m));
        t.mn[i]  = bcast_bits((float)(-m));
        tt = tn;
    }
    return t;
}
__constant__ MTab c_mtab = make_mtab();

// One FISTA solve on the packed pair-of-rows. y: data (packed), x: output (packed).
__device__ __forceinline__ void solve2(const u64* __restrict__ y,
                                       u64* __restrict__ x,
                                       int lane)
{
    const unsigned FULL = 0xffffffffu;
    const u64 C0  = bc(1.0f - C_A - 6.0f * C_B);   // center tap
    const u64 C1  = bc(4.0f * C_B);                // +/-1 taps
    const u64 C2  = bc(-C_B);                      // +/-2 taps
    const u64 CA  = bc(C_A);                       // data-term coefficient
    const u64 B5  = bc(5.0f * C_B);
    const u64 BN2 = bc(-2.0f * C_B);
    const u64 B1  = bc(C_B);

    u64 z[EPL];
    #pragma unroll
    for (int i = 0; i < EPL; i++) { x[i] = y[i]; z[i] = y[i]; }  // proj(y)=y on [0,y]

    const bool l0 = (lane == 0), l31 = (lane == 31);

    #pragma unroll 2
    for (int it = 0; it < NIT; ++it) {
        // 64-bit halo shuffles; zero-pad outside [0, 511]
        u64 zm2 = __shfl_up_sync  (FULL, z[EPL - 2], 1);
        u64 zm1 = __shfl_up_sync  (FULL, z[EPL - 1], 1);
        u64 zp0 = __shfl_down_sync(FULL, z[0], 1);
        u64 zp1 = __shfl_down_sync(FULL, z[1], 1);
        if (l0)  { zm2 = 0ull; zm1 = 0ull; }
        if (l31) { zp0 = 0ull; zp1 = 0ull; }

        // ze[k] = z_global[16*lane - 2 + k], k = 0..19  (snapshot of z)
        u64 ze[EPL + 4];
        ze[0] = zm2; ze[1] = zm1;
        #pragma unroll
        for (int i = 0; i < EPL; i++) ze[2 + i] = z[i];
        ze[EPL + 2] = zp0; ze[EPL + 3] = zp1;

        // momentum coefficients (pre-broadcast u64 pairs, one LDC.64 each)
        const u64 M1P = c_mtab.m1p[it];
        const u64 MN  = c_mtab.mn[it];

        #pragma unroll
        for (int i = 0; i < EPL; i++) {
            // v = CA*y + C0*z + C1*(z[-1]+z[+1]) + C2*(z[-2]+z[+2])
            u64 s1 = add2(ze[i + 1], ze[i + 3]);
            u64 s2 = add2(ze[i],     ze[i + 4]);
            u64 v  = fma2(CA, y[i],
                       fma2(C0, ze[i + 2],
                         fma2(C1, s1, mul2(C2, s2))));

            // exact boundary corrections (true D^T D differs from the
            // zero-padded 5-point at global i = 0, 1, 510, 511); ze snapshot
            // keeps old z values correct
            if (i == 0 && l0) {
                v = fma2(B5,  ze[2], v);
                v = fma2(BN2, ze[3], v);
            }
            if (i == 1 && l0) {
                v = fma2(BN2, ze[2], v);
                v = fma2(B1,  ze[3], v);
            }
            if (i == EPL - 2 && l31) {
                v = fma2(BN2, ze[EPL + 1], v);
                v = fma2(B1,  ze[EPL],     v);
            }
            if (i == EPL - 1 && l31) {
                v = fma2(B5,  ze[EPL + 1], v);
                v = fma2(BN2, ze[EPL],     v);
            }

            // clamp onto [0, y] — scalar FMNMX pairs on alu pipe
            float vl, vh, yl, yh;
            upk(v, vl, vh);
            upk(y[i], yl, yh);
            float xl = fminf(fmaxf(vl, 0.0f), yl);
            float xh = fminf(fmaxf(vh, 0.0f), yh);
            u64 xn = pk(xl, xh);

            // z_new = (1+m) x_new - m x_old
            u64 zn = fma2(M1P, xn, mul2(MN, x[i]));
            x[i] = xn;
            z[i] = zn;
        }
    }
}

__global__ void __launch_bounds__(128, 4)
fista_denoise4_kernel(const float* __restrict__ in, float* __restrict__ out, int npairs)
{
    const int gwarp = (int)((blockIdx.x * (unsigned)blockDim.x + threadIdx.x) >> 5);
    const int lane  = threadIdx.x & 31;
    if (gwarp >= npairs) return;   // whole warp exits together

    const float* r0 = in + (size_t)(2 * gwarp) * ROWN + lane * EPL;
    const float* r1 = r0 + ROWN;

    u64 y[EPL];
    #pragma unroll
    for (int v = 0; v < EPL / 4; v++) {
        float4 a = reinterpret_cast<const float4*>(r0)[v];
        float4 b = reinterpret_cast<const float4*>(r1)[v];
        y[4 * v + 0] = pk(a.x, b.x);
        y[4 * v + 1] = pk(a.y, b.y);
        y[4 * v + 2] = pk(a.z, b.z);
        y[4 * v + 3] = pk(a.w, b.w);
    }

    u64 x[EPL];
    solve2(y, x, lane);                       // pass 1: y = input
    #pragma unroll
    for (int i = 0; i < EPL; i++) y[i] = x[i];
    solve2(y, x, lane);                       // pass 2: y = pass-1 output

    float* w0 = out + (size_t)(2 * gwarp) * ROWN + lane * EPL;
    float* w1 = w0 + ROWN;
    #pragma unroll
    for (int v = 0; v < EPL / 4; v++) {
        float4 a, b;
        upk(x[4 * v + 0], a.x, b.x);
        upk(x[4 * v + 1], a.y, b.y);
        upk(x[4 * v + 2], a.z, b.z);
        upk(x[4 * v + 3], a.w, b.w);
        reinterpret_cast<float4*>(w0)[v] = a;
        reinterpret_cast<float4*>(w1)[v] = b;
    }
}

extern "C" void kernel_launch(void* const* d_in, const int* in_sizes, int n_in,
                              void* d_out, int out_size)
{
    const float* in = (const float*)d_in[0];
    float* out = (float*)d_out;
    const int nelem  = in_sizes[0];           // 32*512*512
    const int nrows  = nelem / ROWN;          // 16384
    const int npairs = nrows / 2;             // 8192 warps
    const int warps_per_block = 128 / 32;     // 4
    const int nblocks = (npairs + warps_per_block - 1) / warps_per_block;
    fista_denoise4_kernel<<<nblocks, 128>>>(in, out, npairs);
}